// round 2
// baseline (speedup 1.0000x reference)
#include <cuda_runtime.h>

// ---------------- scratch (device globals; no runtime allocation) ----------------
__device__ float g_se[4L * 32768 * 128];   // per-head embedded states
__device__ float g_k [4L * 32768 * 128];
__device__ float g_q [4L * 32768 * 128];
__device__ float g_v [4L * 32768 * 32];
__device__ float g_x [32768L * 128];       // concat(head outputs) between stages

#define LEAKY(r) ((r) > 0.f ? (r) : 0.01f * (r))

// ---------------- generic per-head GEMM: out = act(A @ W^T + bias) ----------------
// A: [M x K] row-major (per-head stride sA; 0 = shared across heads)
// W: [N x K] row-major per head (stride sW), bias [N] (stride sB), out [M x N] (stride sO)
__global__ __launch_bounds__(256) void gemm_bias_act(
    const float* __restrict__ A, long sA,
    const float* __restrict__ W, long sW,
    const float* __restrict__ bias, long sB,
    float* __restrict__ out, long sO,
    int M, int N, int K, int leaky)
{
    const int h = blockIdx.z;
    A += (long)h * sA; W += (long)h * sW; bias += (long)h * sB; out += (long)h * sO;

    __shared__ float As[16][65];   // [k][m], padded: conflict-free store & read
    __shared__ float Bs[16][65];   // [k][n]

    const int tid = threadIdx.x;
    const int tx = tid & 15, ty = tid >> 4;
    const int rowBase = blockIdx.y * 64;
    const int colBase = blockIdx.x * 64;

    float acc[4][4] = {};

    for (int kk = 0; kk < K; kk += 16) {
        #pragma unroll
        for (int i = 0; i < 4; i++) {
            int idx = tid + i * 256;
            int m = idx >> 4, k = idx & 15;   // 16 consecutive lanes read 64B contiguous
            As[k][m] = A[(long)(rowBase + m) * K + kk + k];
            int col = colBase + m;
            Bs[k][m] = (col < N) ? W[(long)col * K + kk + k] : 0.f;
        }
        __syncthreads();
        #pragma unroll
        for (int k = 0; k < 16; k++) {
            float a[4], b[4];
            #pragma unroll
            for (int i = 0; i < 4; i++) a[i] = As[k][ty * 4 + i];
            #pragma unroll
            for (int j = 0; j < 4; j++) b[j] = Bs[k][tx * 4 + j];
            #pragma unroll
            for (int i = 0; i < 4; i++)
                #pragma unroll
                for (int j = 0; j < 4; j++)
                    acc[i][j] = fmaf(a[i], b[j], acc[i][j]);
        }
        __syncthreads();
    }

    #pragma unroll
    for (int i = 0; i < 4; i++) {
        int row = rowBase + ty * 4 + i;
        #pragma unroll
        for (int j = 0; j < 4; j++) {
            int col = colBase + tx * 4 + j;
            if (col < N) {
                float r = acc[i][j] + bias[col];
                if (leaky) r = LEAKY(r);
                out[(long)row * N + col] = r;
            }
        }
    }
}

// ---------------- attention: scores -> softmax (write w) -> att = w @ v (write x) ----------------
// q,k: [H][B][64][128], v: [H][B][64][32]
// wout: [H][B][64][64] (goes straight into d_out), xout: [B*64][128] at col h*32
#define ATTN_SMEM ((64 * 128 + 128 * 65 + 64 * 32 + 64 * 65) * 4)

__global__ __launch_bounds__(256) void attn_kernel(
    const float* __restrict__ qg, const float* __restrict__ kg,
    const float* __restrict__ vg,
    float* __restrict__ wout, float* __restrict__ xout, int Bn)
{
    extern __shared__ float sm[];
    float* qs = sm;              // [64][128]
    float* kt = qs + 64 * 128;   // [128][65]  k transposed, padded
    float* vs = kt + 128 * 65;   // [64][32]
    float* ss = vs + 64 * 32;    // [64][65]   scores, padded

    const int b = blockIdx.x, h = blockIdx.y;
    const int tid = threadIdx.x;
    const long base = ((long)h * Bn + b) * 64;
    const float* qp = qg + base * 128;
    const float* kp = kg + base * 128;
    const float* vp = vg + base * 32;

    for (int i = tid; i < 64 * 128; i += 256) {
        qs[i] = qp[i];
        int row = i >> 7, k = i & 127;
        kt[k * 65 + row] = kp[i];
    }
    for (int i = tid; i < 64 * 32; i += 256) vs[i] = vp[i];
    __syncthreads();

    const int tx = tid & 15, ty = tid >> 4;
    float acc[4][4] = {};
    #pragma unroll 4
    for (int k = 0; k < 128; k++) {
        float a[4], bb[4];
        #pragma unroll
        for (int i = 0; i < 4; i++) a[i] = qs[(ty * 4 + i) * 128 + k];
        #pragma unroll
        for (int j = 0; j < 4; j++) bb[j] = kt[k * 65 + tx * 4 + j];
        #pragma unroll
        for (int i = 0; i < 4; i++)
            #pragma unroll
            for (int j = 0; j < 4; j++)
                acc[i][j] = fmaf(a[i], bb[j], acc[i][j]);
    }
    const float scale = 0.088388347648318447f;  // 1/sqrt(128)
    #pragma unroll
    for (int i = 0; i < 4; i++)
        #pragma unroll
        for (int j = 0; j < 4; j++)
            ss[(ty * 4 + i) * 65 + tx * 4 + j] = acc[i][j] * scale;
    __syncthreads();

    if (tid < 64) {   // per-row softmax
        float mx = -1e30f;
        for (int m = 0; m < 64; m++) mx = fmaxf(mx, ss[tid * 65 + m]);
        float s = 0.f;
        for (int m = 0; m < 64; m++) {
            float e = __expf(ss[tid * 65 + m] - mx);
            ss[tid * 65 + m] = e; s += e;
        }
        float inv = 1.f / s;
        for (int m = 0; m < 64; m++) ss[tid * 65 + m] *= inv;
    }
    __syncthreads();

    float* wp = wout + base * 64;
    for (int i = tid; i < 4096; i += 256)
        wp[i] = ss[(i >> 6) * 65 + (i & 63)];

    #pragma unroll
    for (int e = 0; e < 8; e++) {
        int idx = tid + e * 256;
        int n = idx >> 5, o = idx & 31;
        float s = 0.f;
        #pragma unroll 8
        for (int m = 0; m < 64; m++) s = fmaf(ss[n * 65 + m], vs[m * 32 + o], s);
        xout[((long)b * 64 + n) * 128 + h * 32 + o] = s;
    }
}

// ---------------- final MLP + softmax: policy ----------------
#define HEAD_SMEM ((64 * 128 + 128 * 65 + 64 * 64 + 64 * 16 + 64 * 16) * 4)

__global__ __launch_bounds__(256) void head_kernel(
    const float* __restrict__ x,
    const float* __restrict__ F1w, const float* __restrict__ F1b,
    const float* __restrict__ F2w, const float* __restrict__ F2b,
    float* __restrict__ pol)
{
    extern __shared__ float sm[];
    float* xs  = sm;            // [64][128]
    float* f1t = xs + 8192;     // [128][65]  F1 transposed, padded
    float* hs  = f1t + 8320;    // [64][64]
    float* f2t = hs + 4096;     // [64][16]   F2 transposed
    float* ls  = f2t + 1024;    // [64][16]   logits

    const int b = blockIdx.x, tid = threadIdx.x;
    const float* xp = x + (long)b * 64 * 128;

    for (int i = tid; i < 8192; i += 256) {
        xs[i] = xp[i];
        int col = i >> 7, k = i & 127;
        f1t[k * 65 + col] = F1w[i];          // F1w: [64][128]
    }
    for (int i = tid; i < 1024; i += 256) {
        int p = i >> 6, c = i & 63;
        f2t[c * 16 + p] = F2w[i];            // F2w: [16][64]
    }
    __syncthreads();

    const int tx = tid & 15, ty = tid >> 4;
    float acc[4][4] = {};
    #pragma unroll 4
    for (int k = 0; k < 128; k++) {
        float a[4], bb[4];
        #pragma unroll
        for (int i = 0; i < 4; i++) a[i] = xs[(ty * 4 + i) * 128 + k];
        #pragma unroll
        for (int j = 0; j < 4; j++) bb[j] = f1t[k * 65 + tx * 4 + j];
        #pragma unroll
        for (int i = 0; i < 4; i++)
            #pragma unroll
            for (int j = 0; j < 4; j++)
                acc[i][j] = fmaf(a[i], bb[j], acc[i][j]);
    }
    #pragma unroll
    for (int i = 0; i < 4; i++)
        #pragma unroll
        for (int j = 0; j < 4; j++) {
            int col = tx * 4 + j;
            float r = acc[i][j] + F1b[col];
            hs[(ty * 4 + i) * 64 + col] = LEAKY(r);
        }
    __syncthreads();

    #pragma unroll
    for (int e = 0; e < 4; e++) {
        int idx = tid + e * 256;
        int n = idx >> 4, p = idx & 15;
        float s = F2b[p];
        #pragma unroll 8
        for (int c = 0; c < 64; c++) s = fmaf(hs[n * 64 + c], f2t[c * 16 + p], s);
        ls[idx] = s;
    }
    __syncthreads();

    if (tid < 64) {   // softmax over 16 logits
        float mx = -1e30f;
        for (int p = 0; p < 16; p++) mx = fmaxf(mx, ls[tid * 16 + p]);
        float s = 0.f;
        for (int p = 0; p < 16; p++) {
            float e = __expf(ls[tid * 16 + p] - mx);
            ls[tid * 16 + p] = e; s += e;
        }
        float inv = 1.f / s;
        for (int p = 0; p < 16; p++) ls[tid * 16 + p] *= inv;
    }
    __syncthreads();

    float* pp = pol + (long)b * 1024;
    #pragma unroll
    for (int e = 0; e < 4; e++) { int idx = tid + e * 256; pp[idx] = ls[idx]; }
}

// ---------------- launch ----------------
extern "C" void kernel_launch(void* const* d_in, const int* in_sizes, int n_in,
                              void* d_out, int out_size)
{
    const float* states = (const float*)d_in[0];
    const float* E1w = (const float*)d_in[1];  const float* E1b = (const float*)d_in[2];
    const float* K1w = (const float*)d_in[3];  const float* K1b = (const float*)d_in[4];
    const float* Q1w = (const float*)d_in[5];  const float* Q1b = (const float*)d_in[6];
    const float* V1w = (const float*)d_in[7];  const float* V1b = (const float*)d_in[8];
    const float* E2w = (const float*)d_in[9];  const float* E2b = (const float*)d_in[10];
    const float* K2w = (const float*)d_in[11]; const float* K2b = (const float*)d_in[12];
    const float* Q2w = (const float*)d_in[13]; const float* Q2b = (const float*)d_in[14];
    const float* V2w = (const float*)d_in[15]; const float* V2b = (const float*)d_in[16];
    const float* F1w = (const float*)d_in[17]; const float* F1b = (const float*)d_in[18];
    const float* F2w = (const float*)d_in[19]; const float* F2b = (const float*)d_in[20];
    float* out = (float*)d_out;

    float *se, *kk, *qq, *vv, *xx;
    cudaGetSymbolAddress((void**)&se, g_se);
    cudaGetSymbolAddress((void**)&kk, g_k);
    cudaGetSymbolAddress((void**)&qq, g_q);
    cudaGetSymbolAddress((void**)&vv, g_v);
    cudaGetSymbolAddress((void**)&xx, g_x);

    cudaFuncSetAttribute(attn_kernel, cudaFuncAttributeMaxDynamicSharedMemorySize, ATTN_SMEM);
    cudaFuncSetAttribute(head_kernel, cudaFuncAttributeMaxDynamicSharedMemorySize, HEAD_SMEM);

    const long MK = 32768L * 128;
    dim3 blk(256);
    float* w1out = out + 512L * 64 * 16;
    float* w2out = w1out + 4L * 512 * 64 * 64;

    // ---- stage 1 ----
    gemm_bias_act<<<dim3(2, 512, 4), blk>>>(states, 0,        E1w, 128L * 256, E1b, 128, se, MK,          32768, 128, 256, 1);
    gemm_bias_act<<<dim3(2, 512, 4), blk>>>(se,     MK,       K1w, 128L * 128, K1b, 128, kk, MK,          32768, 128, 128, 0);
    gemm_bias_act<<<dim3(2, 512, 4), blk>>>(se,     MK,       Q1w, 128L * 128, Q1b, 128, qq, MK,          32768, 128, 128, 0);
    gemm_bias_act<<<dim3(1, 512, 4), blk>>>(se,     MK,       V1w, 32L * 128,  V1b, 32,  vv, 32768L * 32, 32768, 32,  128, 1);
    attn_kernel<<<dim3(512, 4), blk, ATTN_SMEM>>>(qq, kk, vv, w1out, xx, 512);

    // ---- stage 2 ----
    gemm_bias_act<<<dim3(2, 512, 4), blk>>>(xx,     0,        E2w, 128L * 128, E2b, 128, se, MK,          32768, 128, 128, 1);
    gemm_bias_act<<<dim3(2, 512, 4), blk>>>(se,     MK,       K2w, 128L * 128, K2b, 128, kk, MK,          32768, 128, 128, 0);
    gemm_bias_act<<<dim3(2, 512, 4), blk>>>(se,     MK,       Q2w, 128L * 128, Q2b, 128, qq, MK,          32768, 128, 128, 0);
    gemm_bias_act<<<dim3(1, 512, 4), blk>>>(se,     MK,       V2w, 32L * 128,  V2b, 32,  vv, 32768L * 32, 32768, 32,  128, 1);
    attn_kernel<<<dim3(512, 4), blk, ATTN_SMEM>>>(qq, kk, vv, w2out, xx, 512);

    // ---- policy head ----
    head_kernel<<<512, blk, HEAD_SMEM>>>(xx, F1w, F1b, F2w, F2b, out);
}

// round 6
// speedup vs baseline: 1.0000x; 1.0000x over previous
#include <cuda_runtime.h>

// ---------------- scratch (device globals; no runtime allocation) ----------------
__device__ float g_se[4L * 32768 * 128];   // per-head embedded states
__device__ float g_k [4L * 32768 * 128];
__device__ float g_q [4L * 32768 * 128];
__device__ float g_v [4L * 32768 * 32];
__device__ float g_x [32768L * 128];       // concat(head outputs) between stages

#define LEAKY(r) ((r) > 0.f ? (r) : 0.01f * (r))

// ---------------- generic per-head GEMM: out = act(A @ W^T + bias) ----------------
// A: [M x K] row-major (per-head stride sA; 0 = shared across heads)
// W: [N x K] row-major per head (stride sW), bias [N] (stride sB), out [M x N] (stride sO)
__global__ __launch_bounds__(256) void gemm_bias_act(
    const float* __restrict__ A, long sA,
    const float* __restrict__ W, long sW,
    const float* __restrict__ bias, long sB,
    float* __restrict__ out, long sO,
    int M, int N, int K, int leaky)
{
    const int h = blockIdx.z;
    A += (long)h * sA; W += (long)h * sW; bias += (long)h * sB; out += (long)h * sO;

    __shared__ float As[16][65];   // [k][m], padded: conflict-free store & read
    __shared__ float Bs[16][65];   // [k][n]

    const int tid = threadIdx.x;
    const int tx = tid & 15, ty = tid >> 4;
    const int rowBase = blockIdx.y * 64;
    const int colBase = blockIdx.x * 64;

    float acc[4][4] = {};

    for (int kk = 0; kk < K; kk += 16) {
        #pragma unroll
        for (int i = 0; i < 4; i++) {
            int idx = tid + i * 256;
            int m = idx >> 4, k = idx & 15;   // 16 consecutive lanes read 64B contiguous
            As[k][m] = A[(long)(rowBase + m) * K + kk + k];
            int col = colBase + m;
            Bs[k][m] = (col < N) ? W[(long)col * K + kk + k] : 0.f;
        }
        __syncthreads();
        #pragma unroll
        for (int k = 0; k < 16; k++) {
            float a[4], b[4];
            #pragma unroll
            for (int i = 0; i < 4; i++) a[i] = As[k][ty * 4 + i];
            #pragma unroll
            for (int j = 0; j < 4; j++) b[j] = Bs[k][tx * 4 + j];
            #pragma unroll
            for (int i = 0; i < 4; i++)
                #pragma unroll
                for (int j = 0; j < 4; j++)
                    acc[i][j] = fmaf(a[i], b[j], acc[i][j]);
        }
        __syncthreads();
    }

    #pragma unroll
    for (int i = 0; i < 4; i++) {
        int row = rowBase + ty * 4 + i;
        #pragma unroll
        for (int j = 0; j < 4; j++) {
            int col = colBase + tx * 4 + j;
            if (col < N) {
                float r = acc[i][j] + bias[col];
                if (leaky) r = LEAKY(r);
                out[(long)row * N + col] = r;
            }
        }
    }
}

// ---------------- attention: scores -> softmax (write w) -> att = w @ v (write x) ----------------
// q,k: [H][B][64][128], v: [H][B][64][32]
// wout: [H][B][64][64] (goes straight into d_out), xout: [B*64][128] at col h*32
#define ATTN_SMEM ((64 * 128 + 128 * 65 + 64 * 32 + 64 * 65) * 4)

__global__ __launch_bounds__(256) void attn_kernel(
    const float* __restrict__ qg, const float* __restrict__ kg,
    const float* __restrict__ vg,
    float* __restrict__ wout, float* __restrict__ xout, int Bn)
{
    extern __shared__ float sm[];
    float* qs = sm;              // [64][128]
    float* kt = qs + 64 * 128;   // [128][65]  k transposed, padded
    float* vs = kt + 128 * 65;   // [64][32]
    float* ss = vs + 64 * 32;    // [64][65]   scores, padded

    const int b = blockIdx.x, h = blockIdx.y;
    const int tid = threadIdx.x;
    const long base = ((long)h * Bn + b) * 64;
    const float* qp = qg + base * 128;
    const float* kp = kg + base * 128;
    const float* vp = vg + base * 32;

    for (int i = tid; i < 64 * 128; i += 256) {
        qs[i] = qp[i];
        int row = i >> 7, k = i & 127;
        kt[k * 65 + row] = kp[i];
    }
    for (int i = tid; i < 64 * 32; i += 256) vs[i] = vp[i];
    __syncthreads();

    const int tx = tid & 15, ty = tid >> 4;
    float acc[4][4] = {};
    #pragma unroll 4
    for (int k = 0; k < 128; k++) {
        float a[4], bb[4];
        #pragma unroll
        for (int i = 0; i < 4; i++) a[i] = qs[(ty * 4 + i) * 128 + k];
        #pragma unroll
        for (int j = 0; j < 4; j++) bb[j] = kt[k * 65 + tx * 4 + j];
        #pragma unroll
        for (int i = 0; i < 4; i++)
            #pragma unroll
            for (int j = 0; j < 4; j++)
                acc[i][j] = fmaf(a[i], bb[j], acc[i][j]);
    }
    const float scale = 0.088388347648318447f;  // 1/sqrt(128)
    #pragma unroll
    for (int i = 0; i < 4; i++)
        #pragma unroll
        for (int j = 0; j < 4; j++)
            ss[(ty * 4 + i) * 65 + tx * 4 + j] = acc[i][j] * scale;
    __syncthreads();

    if (tid < 64) {   // per-row softmax
        float mx = -1e30f;
        for (int m = 0; m < 64; m++) mx = fmaxf(mx, ss[tid * 65 + m]);
        float s = 0.f;
        for (int m = 0; m < 64; m++) {
            float e = __expf(ss[tid * 65 + m] - mx);
            ss[tid * 65 + m] = e; s += e;
        }
        float inv = 1.f / s;
        for (int m = 0; m < 64; m++) ss[tid * 65 + m] *= inv;
    }
    __syncthreads();

    float* wp = wout + base * 64;
    for (int i = tid; i < 4096; i += 256)
        wp[i] = ss[(i >> 6) * 65 + (i & 63)];

    #pragma unroll
    for (int e = 0; e < 8; e++) {
        int idx = tid + e * 256;
        int n = idx >> 5, o = idx & 31;
        float s = 0.f;
        #pragma unroll 8
        for (int m = 0; m < 64; m++) s = fmaf(ss[n * 65 + m], vs[m * 32 + o], s);
        xout[((long)b * 64 + n) * 128 + h * 32 + o] = s;
    }
}

// ---------------- final MLP + softmax: policy ----------------
#define HEAD_SMEM ((64 * 128 + 128 * 65 + 64 * 64 + 64 * 16 + 64 * 16) * 4)

__global__ __launch_bounds__(256) void head_kernel(
    const float* __restrict__ x,
    const float* __restrict__ F1w, const float* __restrict__ F1b,
    const float* __restrict__ F2w, const float* __restrict__ F2b,
    float* __restrict__ pol)
{
    extern __shared__ float sm[];
    float* xs  = sm;            // [64][128]
    float* f1t = xs + 8192;     // [128][65]  F1 transposed, padded
    float* hs  = f1t + 8320;    // [64][64]
    float* f2t = hs + 4096;     // [64][16]   F2 transposed
    float* ls  = f2t + 1024;    // [64][16]   logits

    const int b = blockIdx.x, tid = threadIdx.x;
    const float* xp = x + (long)b * 64 * 128;

    for (int i = tid; i < 8192; i += 256) {
        xs[i] = xp[i];
        int col = i >> 7, k = i & 127;
        f1t[k * 65 + col] = F1w[i];          // F1w: [64][128]
    }
    for (int i = tid; i < 1024; i += 256) {
        int p = i >> 6, c = i & 63;
        f2t[c * 16 + p] = F2w[i];            // F2w: [16][64]
    }
    __syncthreads();

    const int tx = tid & 15, ty = tid >> 4;
    float acc[4][4] = {};
    #pragma unroll 4
    for (int k = 0; k < 128; k++) {
        float a[4], bb[4];
        #pragma unroll
        for (int i = 0; i < 4; i++) a[i] = xs[(ty * 4 + i) * 128 + k];
        #pragma unroll
        for (int j = 0; j < 4; j++) bb[j] = f1t[k * 65 + tx * 4 + j];
        #pragma unroll
        for (int i = 0; i < 4; i++)
            #pragma unroll
            for (int j = 0; j < 4; j++)
                acc[i][j] = fmaf(a[i], bb[j], acc[i][j]);
    }
    #pragma unroll
    for (int i = 0; i < 4; i++)
        #pragma unroll
        for (int j = 0; j < 4; j++) {
            int col = tx * 4 + j;
            float r = acc[i][j] + F1b[col];
            hs[(ty * 4 + i) * 64 + col] = LEAKY(r);
        }
    __syncthreads();

    #pragma unroll
    for (int e = 0; e < 4; e++) {
        int idx = tid + e * 256;
        int n = idx >> 4, p = idx & 15;
        float s = F2b[p];
        #pragma unroll 8
        for (int c = 0; c < 64; c++) s = fmaf(hs[n * 64 + c], f2t[c * 16 + p], s);
        ls[idx] = s;
    }
    __syncthreads();

    if (tid < 64) {   // softmax over 16 logits
        float mx = -1e30f;
        for (int p = 0; p < 16; p++) mx = fmaxf(mx, ls[tid * 16 + p]);
        float s = 0.f;
        for (int p = 0; p < 16; p++) {
            float e = __expf(ls[tid * 16 + p] - mx);
            ls[tid * 16 + p] = e; s += e;
        }
        float inv = 1.f / s;
        for (int p = 0; p < 16; p++) ls[tid * 16 + p] *= inv;
    }
    __syncthreads();

    float* pp = pol + (long)b * 1024;
    #pragma unroll
    for (int e = 0; e < 4; e++) { int idx = tid + e * 256; pp[idx] = ls[idx]; }
}

// ---------------- launch ----------------
extern "C" void kernel_launch(void* const* d_in, const int* in_sizes, int n_in,
                              void* d_out, int out_size)
{
    const float* states = (const float*)d_in[0];
    const float* E1w = (const float*)d_in[1];  const float* E1b = (const float*)d_in[2];
    const float* K1w = (const float*)d_in[3];  const float* K1b = (const float*)d_in[4];
    const float* Q1w = (const float*)d_in[5];  const float* Q1b = (const float*)d_in[6];
    const float* V1w = (const float*)d_in[7];  const float* V1b = (const float*)d_in[8];
    const float* E2w = (const float*)d_in[9];  const float* E2b = (const float*)d_in[10];
    const float* K2w = (const float*)d_in[11]; const float* K2b = (const float*)d_in[12];
    const float* Q2w = (const float*)d_in[13]; const float* Q2b = (const float*)d_in[14];
    const float* V2w = (const float*)d_in[15]; const float* V2b = (const float*)d_in[16];
    const float* F1w = (const float*)d_in[17]; const float* F1b = (const float*)d_in[18];
    const float* F2w = (const float*)d_in[19]; const float* F2b = (const float*)d_in[20];
    float* out = (float*)d_out;

    float *se, *kk, *qq, *vv, *xx;
    cudaGetSymbolAddress((void**)&se, g_se);
    cudaGetSymbolAddress((void**)&kk, g_k);
    cudaGetSymbolAddress((void**)&qq, g_q);
    cudaGetSymbolAddress((void**)&vv, g_v);
    cudaGetSymbolAddress((void**)&xx, g_x);

    cudaFuncSetAttribute(attn_kernel, cudaFuncAttributeMaxDynamicSharedMemorySize, ATTN_SMEM);
    cudaFuncSetAttribute(head_kernel, cudaFuncAttributeMaxDynamicSharedMemorySize, HEAD_SMEM);

    const long MK = 32768L * 128;
    dim3 blk(256);
    float* w1out = out + 512L * 64 * 16;
    float* w2out = w1out + 4L * 512 * 64 * 64;

    // ---- stage 1 ----
    gemm_bias_act<<<dim3(2, 512, 4), blk>>>(states, 0,        E1w, 128L * 256, E1b, 128, se, MK,          32768, 128, 256, 1);
    gemm_bias_act<<<dim3(2, 512, 4), blk>>>(se,     MK,       K1w, 128L * 128, K1b, 128, kk, MK,          32768, 128, 128, 0);
    gemm_bias_act<<<dim3(2, 512, 4), blk>>>(se,     MK,       Q1w, 128L * 128, Q1b, 128, qq, MK,          32768, 128, 128, 0);
    gemm_bias_act<<<dim3(1, 512, 4), blk>>>(se,     MK,       V1w, 32L * 128,  V1b, 32,  vv, 32768L * 32, 32768, 32,  128, 1);
    attn_kernel<<<dim3(512, 4), blk, ATTN_SMEM>>>(qq, kk, vv, w1out, xx, 512);

    // ---- stage 2 ----
    gemm_bias_act<<<dim3(2, 512, 4), blk>>>(xx,     0,        E2w, 128L * 128, E2b, 128, se, MK,          32768, 128, 128, 1);
    gemm_bias_act<<<dim3(2, 512, 4), blk>>>(se,     MK,       K2w, 128L * 128, K2b, 128, kk, MK,          32768, 128, 128, 0);
    gemm_bias_act<<<dim3(2, 512, 4), blk>>>(se,     MK,       Q2w, 128L * 128, Q2b, 128, qq, MK,          32768, 128, 128, 0);
    gemm_bias_act<<<dim3(1, 512, 4), blk>>>(se,     MK,       V2w, 32L * 128,  V2b, 32,  vv, 32768L * 32, 32768, 32,  128, 1);
    attn_kernel<<<dim3(512, 4), blk, ATTN_SMEM>>>(qq, kk, vv, w2out, xx, 512);

    // ---- policy head ----
    head_kernel<<<512, blk, HEAD_SMEM>>>(xx, F1w, F1b, F2w, F2b, out);
}

// round 7
// speedup vs baseline: 1.6559x; 1.6558x over previous
#include <cuda_runtime.h>

// ---------------- scratch (device globals; no runtime allocation) ----------------
__device__ float g_se[4L * 32768 * 128];   // per-head embedded states
__device__ float g_k [4L * 32768 * 128];
__device__ float g_q [4L * 32768 * 128];
__device__ float g_v [4L * 32768 * 32];
__device__ float g_x [32768L * 128];       // concat(head outputs) between stages

#define LEAKY(r) ((r) > 0.f ? (r) : 0.01f * (r))

// ================= high-throughput 128-col GEMM: out = act(A @ W^T + bias) =================
// A: [M x K] row-major (per-head stride sA; 0 = shared), W: [128 x K] per head,
// out: [M x 128]. BM=128, BN=128, BK=8, 256 threads, 8x8 microtile (split layout).
__global__ __launch_bounds__(256, 2) void gemm128(
    const float* __restrict__ A, long sA,
    const float* __restrict__ W, long sW,
    const float* __restrict__ bias, long sB,
    float* __restrict__ out, long sO,
    int K, int leaky)
{
    const int h = blockIdx.z;
    A += (long)h * sA; W += (long)h * sW; bias += (long)h * sB; out += (long)h * sO;
    const int rowBase = blockIdx.y * 128;

    __shared__ float As[8 * 132];   // [k][m], pad 132: aligned float4 reads + conflict-free stores
    __shared__ float Bs[8 * 132];   // [k][n]

    const int tid = threadIdx.x;
    const int tx = tid & 15, ty = tid >> 4;
    const int lm = tid >> 1;            // load row 0..127
    const int lk = (tid & 1) << 2;      // k sub-offset 0 or 4

    const float* Ap = A + (long)(rowBase + lm) * K + lk;
    const float* Bp = W + (long)lm * K + lk;

    float acc[8][8] = {};
    float4 aReg = *(const float4*)Ap;
    float4 bReg = *(const float4*)Bp;

    for (int kk = 0; kk < K; kk += 8) {
        As[(lk + 0) * 132 + lm] = aReg.x;
        As[(lk + 1) * 132 + lm] = aReg.y;
        As[(lk + 2) * 132 + lm] = aReg.z;
        As[(lk + 3) * 132 + lm] = aReg.w;
        Bs[(lk + 0) * 132 + lm] = bReg.x;
        Bs[(lk + 1) * 132 + lm] = bReg.y;
        Bs[(lk + 2) * 132 + lm] = bReg.z;
        Bs[(lk + 3) * 132 + lm] = bReg.w;
        __syncthreads();
        if (kk + 8 < K) {                       // prefetch next tile while computing
            aReg = *(const float4*)(Ap + kk + 8);
            bReg = *(const float4*)(Bp + kk + 8);
        }
        #pragma unroll
        for (int k = 0; k < 8; k++) {
            float av[8], bv[8];
            *(float4*)&av[0] = *(const float4*)&As[k * 132 + ty * 4];
            *(float4*)&av[4] = *(const float4*)&As[k * 132 + 64 + ty * 4];
            *(float4*)&bv[0] = *(const float4*)&Bs[k * 132 + tx * 4];
            *(float4*)&bv[4] = *(const float4*)&Bs[k * 132 + 64 + tx * 4];
            #pragma unroll
            for (int i = 0; i < 8; i++)
                #pragma unroll
                for (int j = 0; j < 8; j++)
                    acc[i][j] = fmaf(av[i], bv[j], acc[i][j]);
        }
        __syncthreads();
    }

    float bv0[8];
    #pragma unroll
    for (int j = 0; j < 8; j++)
        bv0[j] = bias[(j < 4 ? tx * 4 + j : 64 + tx * 4 + (j - 4))];

    #pragma unroll
    for (int i = 0; i < 8; i++) {
        int row = rowBase + (i < 4 ? ty * 4 + i : 64 + ty * 4 + (i - 4));
        float r[8];
        #pragma unroll
        for (int j = 0; j < 8; j++) {
            float v = acc[i][j] + bv0[j];
            r[j] = leaky ? LEAKY(v) : v;
        }
        *(float4*)&out[(long)row * 128 + tx * 4]      = *(float4*)&r[0];
        *(float4*)&out[(long)row * 128 + 64 + tx * 4] = *(float4*)&r[4];
    }
}

// ---------------- legacy 64-tile GEMM (kept for the narrow V projections, N=32) ----------------
__global__ __launch_bounds__(256) void gemm_bias_act(
    const float* __restrict__ A, long sA,
    const float* __restrict__ W, long sW,
    const float* __restrict__ bias, long sB,
    float* __restrict__ out, long sO,
    int M, int N, int K, int leaky)
{
    const int h = blockIdx.z;
    A += (long)h * sA; W += (long)h * sW; bias += (long)h * sB; out += (long)h * sO;

    __shared__ float As[16][65];
    __shared__ float Bs[16][65];

    const int tid = threadIdx.x;
    const int tx = tid & 15, ty = tid >> 4;
    const int rowBase = blockIdx.y * 64;
    const int colBase = blockIdx.x * 64;

    float acc[4][4] = {};

    for (int kk = 0; kk < K; kk += 16) {
        #pragma unroll
        for (int i = 0; i < 4; i++) {
            int idx = tid + i * 256;
            int m = idx >> 4, k = idx & 15;
            As[k][m] = A[(long)(rowBase + m) * K + kk + k];
            int col = colBase + m;
            Bs[k][m] = (col < N) ? W[(long)col * K + kk + k] : 0.f;
        }
        __syncthreads();
        #pragma unroll
        for (int k = 0; k < 16; k++) {
            float a[4], b[4];
            #pragma unroll
            for (int i = 0; i < 4; i++) a[i] = As[k][ty * 4 + i];
            #pragma unroll
            for (int j = 0; j < 4; j++) b[j] = Bs[k][tx * 4 + j];
            #pragma unroll
            for (int i = 0; i < 4; i++)
                #pragma unroll
                for (int j = 0; j < 4; j++)
                    acc[i][j] = fmaf(a[i], b[j], acc[i][j]);
        }
        __syncthreads();
    }

    #pragma unroll
    for (int i = 0; i < 4; i++) {
        int row = rowBase + ty * 4 + i;
        #pragma unroll
        for (int j = 0; j < 4; j++) {
            int col = colBase + tx * 4 + j;
            if (col < N) {
                float r = acc[i][j] + bias[col];
                if (leaky) r = LEAKY(r);
                out[(long)row * N + col] = r;
            }
        }
    }
}

// ================= attention (vectorized): scores -> softmax (write w) -> att = w @ v =================
// q,k: [H][B][64][128], v: [H][B][64][32]
// wout: [H][B][64][64] (straight into d_out), xout: [B*64][128] at col h*32
#define ATTN_SMEM ((64 * 128 + 128 * 68 + 64 * 32 + 64 * 68) * 4)

__global__ __launch_bounds__(256) void attn_kernel(
    const float* __restrict__ qg, const float* __restrict__ kg,
    const float* __restrict__ vg,
    float* __restrict__ wout, float* __restrict__ xout, int Bn)
{
    extern __shared__ float sm[];
    float* qs = sm;               // [64][128]
    float* kt = qs + 64 * 128;    // [128][68]  k transposed, padded (16B-aligned rows)
    float* vs = kt + 128 * 68;    // [64][32]
    float* ss = vs + 64 * 32;     // [64][68]   scores, padded

    const int b = blockIdx.x, hh = blockIdx.y;
    const int tid = threadIdx.x;
    const long base = ((long)hh * Bn + b) * 64;
    const float* qp = qg + base * 128;
    const float* kp = kg + base * 128;
    const float* vp = vg + base * 32;

    for (int i = tid; i < 2048; i += 256) ((float4*)qs)[i] = ((const float4*)qp)[i];
    for (int i = tid; i < 512;  i += 256) ((float4*)vs)[i] = ((const float4*)vp)[i];
    for (int i = tid; i < 8192; i += 256) {
        int m = i >> 7, d = i & 127;
        kt[d * 68 + m] = kp[i];
    }
    __syncthreads();

    // -------- scores: 4x4 microtile, 4 d's per step, all LDS.128 --------
    const int tx = tid & 15, ty = tid >> 4;
    float acc[4][4] = {};
    #pragma unroll 4
    for (int d4 = 0; d4 < 32; d4++) {
        float4 a0 = *(const float4*)&qs[(ty * 4 + 0) * 128 + d4 * 4];
        float4 a1 = *(const float4*)&qs[(ty * 4 + 1) * 128 + d4 * 4];
        float4 a2 = *(const float4*)&qs[(ty * 4 + 2) * 128 + d4 * 4];
        float4 a3 = *(const float4*)&qs[(ty * 4 + 3) * 128 + d4 * 4];
        float4 b0 = *(const float4*)&kt[(d4 * 4 + 0) * 68 + tx * 4];
        float4 b1 = *(const float4*)&kt[(d4 * 4 + 1) * 68 + tx * 4];
        float4 b2 = *(const float4*)&kt[(d4 * 4 + 2) * 68 + tx * 4];
        float4 b3 = *(const float4*)&kt[(d4 * 4 + 3) * 68 + tx * 4];
        const float4 aa[4] = {a0, a1, a2, a3};
        #pragma unroll
        for (int i = 0; i < 4; i++)
            #pragma unroll
            for (int j = 0; j < 4; j++) {
                float s = acc[i][j];
                s = fmaf(aa[i].x, (&b0.x)[j], s);
                s = fmaf(aa[i].y, (&b1.x)[j], s);
                s = fmaf(aa[i].z, (&b2.x)[j], s);
                s = fmaf(aa[i].w, (&b3.x)[j], s);
                acc[i][j] = s;
            }
    }
    const float scale = 0.088388347648318447f;  // 1/sqrt(128)
    #pragma unroll
    for (int i = 0; i < 4; i++) {
        float4 r = make_float4(acc[i][0] * scale, acc[i][1] * scale,
                               acc[i][2] * scale, acc[i][3] * scale);
        *(float4*)&ss[(ty * 4 + i) * 68 + tx * 4] = r;
    }
    __syncthreads();

    if (tid < 64) {   // per-row softmax
        float mx = -1e30f;
        for (int m = 0; m < 64; m++) mx = fmaxf(mx, ss[tid * 68 + m]);
        float s = 0.f;
        for (int m = 0; m < 64; m++) {
            float e = __expf(ss[tid * 68 + m] - mx);
            ss[tid * 68 + m] = e; s += e;
        }
        float inv = 1.f / s;
        for (int m = 0; m < 64; m++) ss[tid * 68 + m] *= inv;
    }
    __syncthreads();

    float* wp = wout + base * 64;
    for (int i = tid; i < 4096; i += 256)
        wp[i] = ss[(i >> 6) * 68 + (i & 63)];

    // -------- att = w @ v : each thread -> 2 rows x 4 cols, vectorized --------
    const int o4 = tid & 7;        // col group (o4*4 .. +3)
    const int n0 = tid >> 3;       // rows n0, n0+32
    float r0[4] = {}, r1[4] = {};
    #pragma unroll 4
    for (int m4 = 0; m4 < 16; m4++) {
        float4 aA = *(const float4*)&ss[n0 * 68 + m4 * 4];
        float4 aB = *(const float4*)&ss[(n0 + 32) * 68 + m4 * 4];
        #pragma unroll
        for (int s = 0; s < 4; s++) {
            float4 bb = *(const float4*)&vs[(m4 * 4 + s) * 32 + o4 * 4];
            float am = (&aA.x)[s], bm = (&aB.x)[s];
            #pragma unroll
            for (int j = 0; j < 4; j++) {
                r0[j] = fmaf(am, (&bb.x)[j], r0[j]);
                r1[j] = fmaf(bm, (&bb.x)[j], r1[j]);
            }
        }
    }
    *(float4*)&xout[((long)b * 64 + n0)      * 128 + hh * 32 + o4 * 4] = *(float4*)&r0[0];
    *(float4*)&xout[((long)b * 64 + n0 + 32) * 128 + hh * 32 + o4 * 4] = *(float4*)&r1[0];
}

// ================= final MLP + softmax: policy =================
#define HEAD_SMEM ((64 * 128 + 128 * 68 + 64 * 68 + 64 * 20 + 64 * 16) * 4)

__global__ __launch_bounds__(256) void head_kernel(
    const float* __restrict__ x,
    const float* __restrict__ F1w, const float* __restrict__ F1b,
    const float* __restrict__ F2w, const float* __restrict__ F2b,
    float* __restrict__ pol)
{
    extern __shared__ float sm[];
    float* xs  = sm;              // [64][128]
    float* f1t = xs + 64 * 128;   // [128][68]  F1^T, padded
    float* hs  = f1t + 128 * 68;  // [64][68]
    float* f2t = hs + 64 * 68;    // [64][20]   F2^T, padded
    float* ls  = f2t + 64 * 20;   // [64][16]

    const int b = blockIdx.x, tid = threadIdx.x;
    const float* xp = x + (long)b * 64 * 128;

    for (int i = tid; i < 2048; i += 256) ((float4*)xs)[i] = ((const float4*)xp)[i];
    for (int i = tid; i < 8192; i += 256) {
        int c = i >> 7, d = i & 127;
        f1t[d * 68 + c] = F1w[i];            // F1w: [64][128]
    }
    for (int i = tid; i < 1024; i += 256) {
        int p = i >> 6, c = i & 63;
        f2t[c * 20 + p] = F2w[i];            // F2w: [16][64]
    }
    __syncthreads();

    // -------- h = leaky(x @ F1^T + b) : same vectorized 4x4 pattern --------
    const int tx = tid & 15, ty = tid >> 4;
    float acc[4][4] = {};
    #pragma unroll 4
    for (int d4 = 0; d4 < 32; d4++) {
        float4 a0 = *(const float4*)&xs[(ty * 4 + 0) * 128 + d4 * 4];
        float4 a1 = *(const float4*)&xs[(ty * 4 + 1) * 128 + d4 * 4];
        float4 a2 = *(const float4*)&xs[(ty * 4 + 2) * 128 + d4 * 4];
        float4 a3 = *(const float4*)&xs[(ty * 4 + 3) * 128 + d4 * 4];
        float4 b0 = *(const float4*)&f1t[(d4 * 4 + 0) * 68 + tx * 4];
        float4 b1 = *(const float4*)&f1t[(d4 * 4 + 1) * 68 + tx * 4];
        float4 b2 = *(const float4*)&f1t[(d4 * 4 + 2) * 68 + tx * 4];
        float4 b3 = *(const float4*)&f1t[(d4 * 4 + 3) * 68 + tx * 4];
        const float4 aa[4] = {a0, a1, a2, a3};
        #pragma unroll
        for (int i = 0; i < 4; i++)
            #pragma unroll
            for (int j = 0; j < 4; j++) {
                float s = acc[i][j];
                s = fmaf(aa[i].x, (&b0.x)[j], s);
                s = fmaf(aa[i].y, (&b1.x)[j], s);
                s = fmaf(aa[i].z, (&b2.x)[j], s);
                s = fmaf(aa[i].w, (&b3.x)[j], s);
                acc[i][j] = s;
            }
    }
    #pragma unroll
    for (int i = 0; i < 4; i++) {
        float r[4];
        #pragma unroll
        for (int j = 0; j < 4; j++) {
            float v = acc[i][j] + F1b[tx * 4 + j];
            r[j] = LEAKY(v);
        }
        *(float4*)&hs[(ty * 4 + i) * 68 + tx * 4] = *(float4*)&r[0];
    }
    __syncthreads();

    // -------- logits = h @ F2^T + b : each thread -> 1 row x 4 cols --------
    {
        const int p4 = tid & 3;
        const int n  = tid >> 2;
        float acc2[4];
        #pragma unroll
        for (int j = 0; j < 4; j++) acc2[j] = F2b[p4 * 4 + j];
        #pragma unroll 4
        for (int c4 = 0; c4 < 16; c4++) {
            float4 a = *(const float4*)&hs[n * 68 + c4 * 4];
            #pragma unroll
            for (int s = 0; s < 4; s++) {
                float4 bb = *(const float4*)&f2t[(c4 * 4 + s) * 20 + p4 * 4];
                float am = (&a.x)[s];
                #pragma unroll
                for (int j = 0; j < 4; j++)
                    acc2[j] = fmaf(am, (&bb.x)[j], acc2[j]);
            }
        }
        *(float4*)&ls[n * 16 + p4 * 4] = *(float4*)&acc2[0];
    }
    __syncthreads();

    if (tid < 64) {   // softmax over 16 logits
        float mx = -1e30f;
        for (int p = 0; p < 16; p++) mx = fmaxf(mx, ls[tid * 16 + p]);
        float s = 0.f;
        for (int p = 0; p < 16; p++) {
            float e = __expf(ls[tid * 16 + p] - mx);
            ls[tid * 16 + p] = e; s += e;
        }
        float inv = 1.f / s;
        for (int p = 0; p < 16; p++) ls[tid * 16 + p] *= inv;
    }
    __syncthreads();

    float* pp = pol + (long)b * 1024;
    #pragma unroll
    for (int e = 0; e < 4; e++) { int idx = tid + e * 256; pp[idx] = ls[idx]; }
}

// ---------------- launch ----------------
extern "C" void kernel_launch(void* const* d_in, const int* in_sizes, int n_in,
                              void* d_out, int out_size)
{
    const float* states = (const float*)d_in[0];
    const float* E1w = (const float*)d_in[1];  const float* E1b = (const float*)d_in[2];
    const float* K1w = (const float*)d_in[3];  const float* K1b = (const float*)d_in[4];
    const float* Q1w = (const float*)d_in[5];  const float* Q1b = (const float*)d_in[6];
    const float* V1w = (const float*)d_in[7];  const float* V1b = (const float*)d_in[8];
    const float* E2w = (const float*)d_in[9];  const float* E2b = (const float*)d_in[10];
    const float* K2w = (const float*)d_in[11]; const float* K2b = (const float*)d_in[12];
    const float* Q2w = (const float*)d_in[13]; const float* Q2b = (const float*)d_in[14];
    const float* V2w = (const float*)d_in[15]; const float* V2b = (const float*)d_in[16];
    const float* F1w = (const float*)d_in[17]; const float* F1b = (const float*)d_in[18];
    const float* F2w = (const float*)d_in[19]; const float* F2b = (const float*)d_in[20];
    float* out = (float*)d_out;

    float *se, *kk, *qq, *vv, *xx;
    cudaGetSymbolAddress((void**)&se, g_se);
    cudaGetSymbolAddress((void**)&kk, g_k);
    cudaGetSymbolAddress((void**)&qq, g_q);
    cudaGetSymbolAddress((void**)&vv, g_v);
    cudaGetSymbolAddress((void**)&xx, g_x);

    cudaFuncSetAttribute(attn_kernel, cudaFuncAttributeMaxDynamicSharedMemorySize, ATTN_SMEM);
    cudaFuncSetAttribute(head_kernel, cudaFuncAttributeMaxDynamicSharedMemorySize, HEAD_SMEM);

    const long MK = 32768L * 128;
    dim3 blk(256);
    float* w1out = out + 512L * 64 * 16;
    float* w2out = w1out + 4L * 512 * 64 * 64;

    // ---- stage 1 ----
    gemm128<<<dim3(1, 256, 4), blk>>>(states, 0,  E1w, 128L * 256, E1b, 128, se, MK, 256, 1);
    gemm128<<<dim3(1, 256, 4), blk>>>(se,     MK, K1w, 128L * 128, K1b, 128, kk, MK, 128, 0);
    gemm128<<<dim3(1, 256, 4), blk>>>(se,     MK, Q1w, 128L * 128, Q1b, 128, qq, MK, 128, 0);
    gemm_bias_act<<<dim3(1, 512, 4), blk>>>(se, MK, V1w, 32L * 128, V1b, 32, vv, 32768L * 32, 32768, 32, 128, 1);
    attn_kernel<<<dim3(512, 4), blk, ATTN_SMEM>>>(qq, kk, vv, w1out, xx, 512);

    // ---- stage 2 ----
    gemm128<<<dim3(1, 256, 4), blk>>>(xx,     0,  E2w, 128L * 128, E2b, 128, se, MK, 128, 1);
    gemm128<<<dim3(1, 256, 4), blk>>>(se,     MK, K2w, 128L * 128, K2b, 128, kk, MK, 128, 0);
    gemm128<<<dim3(1, 256, 4), blk>>>(se,     MK, Q2w, 128L * 128, Q2b, 128, qq, MK, 128, 0);
    gemm_bias_act<<<dim3(1, 512, 4), blk>>>(se, MK, V2w, 32L * 128, V2b, 32, vv, 32768L * 32, 32768, 32, 128, 1);
    attn_kernel<<<dim3(512, 4), blk, ATTN_SMEM>>>(qq, kk, vv, w2out, xx, 512);

    // ---- policy head ----
    head_kernel<<<512, blk, HEAD_SMEM>>>(xx, F1w, F1b, F2w, F2b, out);
}

// round 11
// speedup vs baseline: 2.5874x; 1.5626x over previous
#include <cuda_runtime.h>
#include <cuda_bf16.h>
#include <cstdint>

// ---------------- scratch (device globals; no runtime allocation) ----------------
__device__ float g_se[4L * 32768 * 128];
__device__ float g_k [4L * 32768 * 128];
__device__ float g_q [4L * 32768 * 128];
__device__ float g_v [4L * 32768 * 32];
__device__ float g_x [32768L * 128];

#define LEAKY(r) ((r) > 0.f ? (r) : 0.01f * (r))

// ================= helpers =================
__device__ __forceinline__ uint32_t smem_u32(const void* p) {
    uint32_t a;
    asm("{ .reg .u64 t; cvta.to.shared.u64 t, %1; cvt.u32.u64 %0, t; }" : "=r"(a) : "l"(p));
    return a;
}
__device__ __forceinline__ void ldsm_x4(uint32_t r[4], uint32_t addr) {
    asm volatile("ldmatrix.sync.aligned.m8n8.x4.shared.b16 {%0,%1,%2,%3}, [%4];"
                 : "=r"(r[0]), "=r"(r[1]), "=r"(r[2]), "=r"(r[3]) : "r"(addr));
}
__device__ __forceinline__ void mma16816(float d[4], const uint32_t a[4], const uint32_t b[2]) {
    asm volatile("mma.sync.aligned.m16n8k16.row.col.f32.bf16.bf16.f32 "
                 "{%0,%1,%2,%3}, {%4,%5,%6,%7}, {%8,%9}, {%0,%1,%2,%3};"
                 : "+f"(d[0]), "+f"(d[1]), "+f"(d[2]), "+f"(d[3])
                 : "r"(a[0]), "r"(a[1]), "r"(a[2]), "r"(a[3]), "r"(b[0]), "r"(b[1]));
}

// convert float4 -> 4 bf16 hi (8B) + 4 bf16 lo (8B), store at byte offset
__device__ __forceinline__ void cvt_store(float4 v, char* hiB, char* loB, uint32_t off) {
    __nv_bfloat16 h0 = __float2bfloat16(v.x), h1 = __float2bfloat16(v.y);
    __nv_bfloat16 h2 = __float2bfloat16(v.z), h3 = __float2bfloat16(v.w);
    __nv_bfloat16 l0 = __float2bfloat16(v.x - __bfloat162float(h0));
    __nv_bfloat16 l1 = __float2bfloat16(v.y - __bfloat162float(h1));
    __nv_bfloat16 l2 = __float2bfloat16(v.z - __bfloat162float(h2));
    __nv_bfloat16 l3 = __float2bfloat16(v.w - __bfloat162float(h3));
    uint2 hw, lw;
    hw.x = (uint32_t)__bfloat16_as_ushort(h0) | ((uint32_t)__bfloat16_as_ushort(h1) << 16);
    hw.y = (uint32_t)__bfloat16_as_ushort(h2) | ((uint32_t)__bfloat16_as_ushort(h3) << 16);
    lw.x = (uint32_t)__bfloat16_as_ushort(l0) | ((uint32_t)__bfloat16_as_ushort(l1) << 16);
    lw.y = (uint32_t)__bfloat16_as_ushort(l2) | ((uint32_t)__bfloat16_as_ushort(l3) << 16);
    *(uint2*)(hiB + off) = hw;
    *(uint2*)(loB + off) = lw;
}

// ================= HMMA GEMM: out = act(A @ W^T + bias), split-bf16 fp32-equivalent =================
// A: [M x K] (per-head stride sA; 0 = shared), W: [N_COLS x K] per head, out [M x N_COLS].
// Tile: 128 rows x N_COLS cols. K chunked by 64. Smem rows padded to 72 bf16 (144B).
#define MG_PAD 144                       // bytes per smem row
#define MG_SMEM(N) (2 * 128 * MG_PAD + 2 * (N) * MG_PAD)

template <int N_COLS>
__global__ __launch_bounds__(256) void mgemm(
    const float* __restrict__ A, long sA,
    const float* __restrict__ W, long sW,
    const float* __restrict__ bias, long sB,
    float* __restrict__ out, long sO,
    int K, int leaky)
{
    extern __shared__ char smc[];
    char* smA_hi = smc;
    char* smA_lo = smc + 128 * MG_PAD;
    char* smW_hi = smc + 256 * MG_PAD;
    char* smW_lo = smW_hi + N_COLS * MG_PAD;
    const uint32_t base = smem_u32(smc);
    const uint32_t A_HI = base;
    const uint32_t A_LO = base + 128 * MG_PAD;
    const uint32_t W_HI = base + 256 * MG_PAD;
    const uint32_t W_LO = W_HI + N_COLS * MG_PAD;

    const int h = blockIdx.z;
    A += (long)h * sA; W += (long)h * sW; bias += (long)h * sB; out += (long)h * sO;
    const int rowBase = blockIdx.y * 128;
    const int tid = threadIdx.x;
    const int w = tid >> 5, lane = tid & 31;

    constexpr int MW = (N_COLS == 128) ? 2 : 1;   // m16 atoms per warp
    constexpr int NW = (N_COLS == 128) ? 8 : 4;   // n8 atoms per warp
    const int wrow = (N_COLS == 128) ? (w >> 1) * 32 : w * 16;
    const int wcol = (N_COLS == 128) ? (w & 1) * 64 : 0;

    // ldmatrix lane->address components
    const int aRow = wrow + (lane & 15);
    const int aColB = ((lane >> 4) << 3) * 2;                 // +0 or +16 bytes
    const int bN = ((lane >> 4) << 3) + (lane & 7);
    const int bKB = (((lane >> 3) & 1) << 3) * 2;             // +0 or +16 bytes

    float acc[MW][NW][4] = {};

    for (int kc = 0; kc < K; kc += 64) {
        // ---- convert A chunk [128 x 64] fp32 -> hi/lo bf16 ----
        #pragma unroll
        for (int it = 0; it < 8; it++) {
            int idx = tid + it * 256;
            int row = idx >> 4, c4 = (idx & 15) << 2;
            float4 v = *(const float4*)&A[(long)(rowBase + row) * K + kc + c4];
            cvt_store(v, smA_hi, smA_lo, (uint32_t)(row * MG_PAD + c4 * 2));
        }
        // ---- convert W chunk [N_COLS x 64] ----
        for (int idx = tid; idx < N_COLS * 16; idx += 256) {
            int row = idx >> 4, c4 = (idx & 15) << 2;
            float4 v = *(const float4*)&W[(long)row * K + kc + c4];
            cvt_store(v, smW_hi, smW_lo, (uint32_t)(row * MG_PAD + c4 * 2));
        }
        __syncthreads();

        #pragma unroll
        for (int ks = 0; ks < 4; ks++) {
            const uint32_t k0B = (uint32_t)(ks * 16) * 2;
            uint32_t ah[MW][4], al[MW][4];
            #pragma unroll
            for (int mi = 0; mi < MW; mi++) {
                uint32_t ao = (uint32_t)((aRow + mi * 16) * MG_PAD) + k0B + aColB;
                ldsm_x4(ah[mi], A_HI + ao);
                ldsm_x4(al[mi], A_LO + ao);
            }
            #pragma unroll
            for (int np = 0; np < NW / 2; np++) {
                uint32_t bo = (uint32_t)((wcol + np * 16 + bN) * MG_PAD) + k0B + bKB;
                uint32_t bh[4], bl[4];
                ldsm_x4(bh, W_HI + bo);
                ldsm_x4(bl, W_LO + bo);
                #pragma unroll
                for (int mi = 0; mi < MW; mi++)
                    #pragma unroll
                    for (int s = 0; s < 2; s++) {
                        mma16816(acc[mi][np * 2 + s], ah[mi], &bh[2 * s]);
                        mma16816(acc[mi][np * 2 + s], ah[mi], &bl[2 * s]);
                        mma16816(acc[mi][np * 2 + s], al[mi], &bh[2 * s]);
                    }
            }
        }
        __syncthreads();
    }

    // ---- epilogue: fragment -> bias + leaky -> float2 stores ----
    const int g = lane >> 2, t = lane & 3;
    #pragma unroll
    for (int mi = 0; mi < MW; mi++) {
        #pragma unroll
        for (int ni = 0; ni < NW; ni++) {
            int col = wcol + ni * 8 + 2 * t;
            float b0 = bias[col], b1 = bias[col + 1];
            int r0 = rowBase + wrow + mi * 16 + g;
            float v0 = acc[mi][ni][0] + b0, v1 = acc[mi][ni][1] + b1;
            float v2 = acc[mi][ni][2] + b0, v3 = acc[mi][ni][3] + b1;
            if (leaky) { v0 = LEAKY(v0); v1 = LEAKY(v1); v2 = LEAKY(v2); v3 = LEAKY(v3); }
            *(float2*)&out[(long)r0 * N_COLS + col]       = make_float2(v0, v1);
            *(float2*)&out[(long)(r0 + 8) * N_COLS + col] = make_float2(v2, v3);
        }
    }
}

// ================= attention (fp32, vectorized) =================
#define ATTN_SMEM ((64 * 128 + 128 * 68 + 64 * 32 + 64 * 68) * 4)

__global__ __launch_bounds__(256) void attn_kernel(
    const float* __restrict__ qg, const float* __restrict__ kg,
    const float* __restrict__ vg,
    float* __restrict__ wout, float* __restrict__ xout, int Bn)
{
    extern __shared__ float sm[];
    float* qs = sm;
    float* kt = qs + 64 * 128;
    float* vs = kt + 128 * 68;
    float* ss = vs + 64 * 32;

    const int b = blockIdx.x, hh = blockIdx.y;
    const int tid = threadIdx.x;
    const long base = ((long)hh * Bn + b) * 64;
    const float* qp = qg + base * 128;
    const float* kp = kg + base * 128;
    const float* vp = vg + base * 32;

    for (int i = tid; i < 2048; i += 256) ((float4*)qs)[i] = ((const float4*)qp)[i];
    for (int i = tid; i < 512;  i += 256) ((float4*)vs)[i] = ((const float4*)vp)[i];
    for (int i = tid; i < 8192; i += 256) {
        int m = i >> 7, d = i & 127;
        kt[d * 68 + m] = kp[i];
    }
    __syncthreads();

    const int tx = tid & 15, ty = tid >> 4;
    float acc[4][4] = {};
    #pragma unroll 4
    for (int d4 = 0; d4 < 32; d4++) {
        float4 a0 = *(const float4*)&qs[(ty * 4 + 0) * 128 + d4 * 4];
        float4 a1 = *(const float4*)&qs[(ty * 4 + 1) * 128 + d4 * 4];
        float4 a2 = *(const float4*)&qs[(ty * 4 + 2) * 128 + d4 * 4];
        float4 a3 = *(const float4*)&qs[(ty * 4 + 3) * 128 + d4 * 4];
        float4 b0 = *(const float4*)&kt[(d4 * 4 + 0) * 68 + tx * 4];
        float4 b1 = *(const float4*)&kt[(d4 * 4 + 1) * 68 + tx * 4];
        float4 b2 = *(const float4*)&kt[(d4 * 4 + 2) * 68 + tx * 4];
        float4 b3 = *(const float4*)&kt[(d4 * 4 + 3) * 68 + tx * 4];
        const float4 aa[4] = {a0, a1, a2, a3};
        #pragma unroll
        for (int i = 0; i < 4; i++)
            #pragma unroll
            for (int j = 0; j < 4; j++) {
                float s = acc[i][j];
                s = fmaf(aa[i].x, (&b0.x)[j], s);
                s = fmaf(aa[i].y, (&b1.x)[j], s);
                s = fmaf(aa[i].z, (&b2.x)[j], s);
                s = fmaf(aa[i].w, (&b3.x)[j], s);
                acc[i][j] = s;
            }
    }
    const float scale = 0.088388347648318447f;
    #pragma unroll
    for (int i = 0; i < 4; i++) {
        float4 r = make_float4(acc[i][0] * scale, acc[i][1] * scale,
                               acc[i][2] * scale, acc[i][3] * scale);
        *(float4*)&ss[(ty * 4 + i) * 68 + tx * 4] = r;
    }
    __syncthreads();

    if (tid < 64) {
        float mx = -1e30f;
        for (int m = 0; m < 64; m++) mx = fmaxf(mx, ss[tid * 68 + m]);
        float s = 0.f;
        for (int m = 0; m < 64; m++) {
            float e = __expf(ss[tid * 68 + m] - mx);
            ss[tid * 68 + m] = e; s += e;
        }
        float inv = 1.f / s;
        for (int m = 0; m < 64; m++) ss[tid * 68 + m] *= inv;
    }
    __syncthreads();

    float* wp = wout + base * 64;
    for (int i = tid; i < 4096; i += 256)
        wp[i] = ss[(i >> 6) * 68 + (i & 63)];

    const int o4 = tid & 7;
    const int n0 = tid >> 3;
    float r0[4] = {}, r1[4] = {};
    #pragma unroll 4
    for (int m4 = 0; m4 < 16; m4++) {
        float4 aA = *(const float4*)&ss[n0 * 68 + m4 * 4];
        float4 aB = *(const float4*)&ss[(n0 + 32) * 68 + m4 * 4];
        #pragma unroll
        for (int s = 0; s < 4; s++) {
            float4 bb = *(const float4*)&vs[(m4 * 4 + s) * 32 + o4 * 4];
            float am = (&aA.x)[s], bm = (&aB.x)[s];
            #pragma unroll
            for (int j = 0; j < 4; j++) {
                r0[j] = fmaf(am, (&bb.x)[j], r0[j]);
                r1[j] = fmaf(bm, (&bb.x)[j], r1[j]);
            }
        }
    }
    *(float4*)&xout[((long)b * 64 + n0)      * 128 + hh * 32 + o4 * 4] = *(float4*)&r0[0];
    *(float4*)&xout[((long)b * 64 + n0 + 32) * 128 + hh * 32 + o4 * 4] = *(float4*)&r1[0];
}

// ================= final MLP + softmax =================
#define HEAD_SMEM ((64 * 128 + 128 * 68 + 64 * 68 + 64 * 20 + 64 * 16) * 4)

__global__ __launch_bounds__(256) void head_kernel(
    const float* __restrict__ x,
    const float* __restrict__ F1w, const float* __restrict__ F1b,
    const float* __restrict__ F2w, const float* __restrict__ F2b,
    float* __restrict__ pol)
{
    extern __shared__ float sm[];
    float* xs  = sm;
    float* f1t = xs + 64 * 128;
    float* hs  = f1t + 128 * 68;
    float* f2t = hs + 64 * 68;
    float* ls  = f2t + 64 * 20;

    const int b = blockIdx.x, tid = threadIdx.x;
    const float* xp = x + (long)b * 64 * 128;

    for (int i = tid; i < 2048; i += 256) ((float4*)xs)[i] = ((const float4*)xp)[i];
    for (int i = tid; i < 8192; i += 256) {
        int c = i >> 7, d = i & 127;
        f1t[d * 68 + c] = F1w[i];
    }
    for (int i = tid; i < 1024; i += 256) {
        int p = i >> 6, c = i & 63;
        f2t[c * 20 + p] = F2w[i];
    }
    __syncthreads();

    const int tx = tid & 15, ty = tid >> 4;
    float acc[4][4] = {};
    #pragma unroll 4
    for (int d4 = 0; d4 < 32; d4++) {
        float4 a0 = *(const float4*)&xs[(ty * 4 + 0) * 128 + d4 * 4];
        float4 a1 = *(const float4*)&xs[(ty * 4 + 1) * 128 + d4 * 4];
        float4 a2 = *(const float4*)&xs[(ty * 4 + 2) * 128 + d4 * 4];
        float4 a3 = *(const float4*)&xs[(ty * 4 + 3) * 128 + d4 * 4];
        float4 b0 = *(const float4*)&f1t[(d4 * 4 + 0) * 68 + tx * 4];
        float4 b1 = *(const float4*)&f1t[(d4 * 4 + 1) * 68 + tx * 4];
        float4 b2 = *(const float4*)&f1t[(d4 * 4 + 2) * 68 + tx * 4];
        float4 b3 = *(const float4*)&f1t[(d4 * 4 + 3) * 68 + tx * 4];
        const float4 aa[4] = {a0, a1, a2, a3};
        #pragma unroll
        for (int i = 0; i < 4; i++)
            #pragma unroll
            for (int j = 0; j < 4; j++) {
                float s = acc[i][j];
                s = fmaf(aa[i].x, (&b0.x)[j], s);
                s = fmaf(aa[i].y, (&b1.x)[j], s);
                s = fmaf(aa[i].z, (&b2.x)[j], s);
                s = fmaf(aa[i].w, (&b3.x)[j], s);
                acc[i][j] = s;
            }
    }
    #pragma unroll
    for (int i = 0; i < 4; i++) {
        float r[4];
        #pragma unroll
        for (int j = 0; j < 4; j++) {
            float v = acc[i][j] + F1b[tx * 4 + j];
            r[j] = LEAKY(v);
        }
        *(float4*)&hs[(ty * 4 + i) * 68 + tx * 4] = *(float4*)&r[0];
    }
    __syncthreads();

    {
        const int p4 = tid & 3;
        const int n  = tid >> 2;
        float acc2[4];
        #pragma unroll
        for (int j = 0; j < 4; j++) acc2[j] = F2b[p4 * 4 + j];
        #pragma unroll 4
        for (int c4 = 0; c4 < 16; c4++) {
            float4 a = *(const float4*)&hs[n * 68 + c4 * 4];
            #pragma unroll
            for (int s = 0; s < 4; s++) {
                float4 bb = *(const float4*)&f2t[(c4 * 4 + s) * 20 + p4 * 4];
                float am = (&a.x)[s];
                #pragma unroll
                for (int j = 0; j < 4; j++)
                    acc2[j] = fmaf(am, (&bb.x)[j], acc2[j]);
            }
        }
        *(float4*)&ls[n * 16 + p4 * 4] = *(float4*)&acc2[0];
    }
    __syncthreads();

    if (tid < 64) {
        float mx = -1e30f;
        for (int p = 0; p < 16; p++) mx = fmaxf(mx, ls[tid * 16 + p]);
        float s = 0.f;
        for (int p = 0; p < 16; p++) {
            float e = __expf(ls[tid * 16 + p] - mx);
            ls[tid * 16 + p] = e; s += e;
        }
        float inv = 1.f / s;
        for (int p = 0; p < 16; p++) ls[tid * 16 + p] *= inv;
    }
    __syncthreads();

    float* pp = pol + (long)b * 1024;
    #pragma unroll
    for (int e = 0; e < 4; e++) { int idx = tid + e * 256; pp[idx] = ls[idx]; }
}

// ---------------- launch ----------------
extern "C" void kernel_launch(void* const* d_in, const int* in_sizes, int n_in,
                              void* d_out, int out_size)
{
    const float* states = (const float*)d_in[0];
    const float* E1w = (const float*)d_in[1];  const float* E1b = (const float*)d_in[2];
    const float* K1w = (const float*)d_in[3];  const float* K1b = (const float*)d_in[4];
    const float* Q1w = (const float*)d_in[5];  const float* Q1b = (const float*)d_in[6];
    const float* V1w = (const float*)d_in[7];  const float* V1b = (const float*)d_in[8];
    const float* E2w = (const float*)d_in[9];  const float* E2b = (const float*)d_in[10];
    const float* K2w = (const float*)d_in[11]; const float* K2b = (const float*)d_in[12];
    const float* Q2w = (const float*)d_in[13]; const float* Q2b = (const float*)d_in[14];
    const float* V2w = (const float*)d_in[15]; const float* V2b = (const float*)d_in[16];
    const float* F1w = (const float*)d_in[17]; const float* F1b = (const float*)d_in[18];
    const float* F2w = (const float*)d_in[19]; const float* F2b = (const float*)d_in[20];
    float* out = (float*)d_out;

    float *se, *kk, *qq, *vv, *xx;
    cudaGetSymbolAddress((void**)&se, g_se);
    cudaGetSymbolAddress((void**)&kk, g_k);
    cudaGetSymbolAddress((void**)&qq, g_q);
    cudaGetSymbolAddress((void**)&vv, g_v);
    cudaGetSymbolAddress((void**)&xx, g_x);

    cudaFuncSetAttribute(mgemm<128>, cudaFuncAttributeMaxDynamicSharedMemorySize, MG_SMEM(128));
    cudaFuncSetAttribute(mgemm<32>,  cudaFuncAttributeMaxDynamicSharedMemorySize, MG_SMEM(32));
    cudaFuncSetAttribute(attn_kernel, cudaFuncAttributeMaxDynamicSharedMemorySize, ATTN_SMEM);
    cudaFuncSetAttribute(head_kernel, cudaFuncAttributeMaxDynamicSharedMemorySize, HEAD_SMEM);

    const long MK = 32768L * 128;
    dim3 blk(256);
    dim3 g128(1, 256, 4);
    float* w1out = out + 512L * 64 * 16;
    float* w2out = w1out + 4L * 512 * 64 * 64;

    // ---- stage 1 ----
    mgemm<128><<<g128, blk, MG_SMEM(128)>>>(states, 0,  E1w, 128L * 256, E1b, 128, se, MK, 256, 1);
    mgemm<128><<<g128, blk, MG_SMEM(128)>>>(se,     MK, K1w, 128L * 128, K1b, 128, kk, MK, 128, 0);
    mgemm<128><<<g128, blk, MG_SMEM(128)>>>(se,     MK, Q1w, 128L * 128, Q1b, 128, qq, MK, 128, 0);
    mgemm<32> <<<g128, blk, MG_SMEM(32)>>> (se,     MK, V1w, 32L * 128,  V1b, 32,  vv, 32768L * 32, 128, 1);
    attn_kernel<<<dim3(512, 4), blk, ATTN_SMEM>>>(qq, kk, vv, w1out, xx, 512);

    // ---- stage 2 ----
    mgemm<128><<<g128, blk, MG_SMEM(128)>>>(xx,     0,  E2w, 128L * 128, E2b, 128, se, MK, 128, 1);
    mgemm<128><<<g128, blk, MG_SMEM(128)>>>(se,     MK, K2w, 128L * 128, K2b, 128, kk, MK, 128, 0);
    mgemm<128><<<g128, blk, MG_SMEM(128)>>>(se,     MK, Q2w, 128L * 128, Q2b, 128, qq, MK, 128, 0);
    mgemm<32> <<<g128, blk, MG_SMEM(32)>>> (se,     MK, V2w, 32L * 128,  V2b, 32,  vv, 32768L * 32, 128, 1);
    attn_kernel<<<dim3(512, 4), blk, ATTN_SMEM>>>(qq, kk, vv, w2out, xx, 512);

    // ---- policy head ----
    head_kernel<<<512, blk, HEAD_SMEM>>>(xx, F1w, F1b, F2w, F2b, out);
}

// round 13
// speedup vs baseline: 2.9391x; 1.1359x over previous
#include <cuda_runtime.h>
#include <cuda_bf16.h>
#include <cstdint>

// ---------------- scratch ----------------
__device__ float g_x [32768L * 128];       // stage-1 output
__device__ float g_x2[32768L * 128];       // stage-2 output

#define LEAKY(r) ((r) > 0.f ? (r) : 0.01f * (r))

// ================= helpers =================
__device__ __forceinline__ uint32_t smem_u32(const void* p) {
    uint32_t a;
    asm("{ .reg .u64 t; cvta.to.shared.u64 t, %1; cvt.u32.u64 %0, t; }" : "=r"(a) : "l"(p));
    return a;
}
__device__ __forceinline__ void ldsm_x4(uint32_t r[4], uint32_t addr) {
    asm volatile("ldmatrix.sync.aligned.m8n8.x4.shared.b16 {%0,%1,%2,%3}, [%4];"
                 : "=r"(r[0]), "=r"(r[1]), "=r"(r[2]), "=r"(r[3]) : "r"(addr));
}
__device__ __forceinline__ void mma16816(float d[4], const uint32_t a[4], const uint32_t b[2]) {
    asm volatile("mma.sync.aligned.m16n8k16.row.col.f32.bf16.bf16.f32 "
                 "{%0,%1,%2,%3}, {%4,%5,%6,%7}, {%8,%9}, {%0,%1,%2,%3};"
                 : "+f"(d[0]), "+f"(d[1]), "+f"(d[2]), "+f"(d[3])
                 : "r"(a[0]), "r"(a[1]), "r"(a[2]), "r"(a[3]), "r"(b[0]), "r"(b[1]));
}
// float4 -> 4 bf16 hi (8B) + 4 bf16 lo (8B) at byte offset
__device__ __forceinline__ void cvt_store(float4 v, char* hiB, char* loB, uint32_t off) {
    __nv_bfloat16 h0 = __float2bfloat16(v.x), h1 = __float2bfloat16(v.y);
    __nv_bfloat16 h2 = __float2bfloat16(v.z), h3 = __float2bfloat16(v.w);
    __nv_bfloat16 l0 = __float2bfloat16(v.x - __bfloat162float(h0));
    __nv_bfloat16 l1 = __float2bfloat16(v.y - __bfloat162float(h1));
    __nv_bfloat16 l2 = __float2bfloat16(v.z - __bfloat162float(h2));
    __nv_bfloat16 l3 = __float2bfloat16(v.w - __bfloat162float(h3));
    uint2 hw, lw;
    hw.x = (uint32_t)__bfloat16_as_ushort(h0) | ((uint32_t)__bfloat16_as_ushort(h1) << 16);
    hw.y = (uint32_t)__bfloat16_as_ushort(h2) | ((uint32_t)__bfloat16_as_ushort(h3) << 16);
    lw.x = (uint32_t)__bfloat16_as_ushort(l0) | ((uint32_t)__bfloat16_as_ushort(l1) << 16);
    lw.y = (uint32_t)__bfloat16_as_ushort(l2) | ((uint32_t)__bfloat16_as_ushort(l3) << 16);
    *(uint2*)(hiB + off) = hw;
    *(uint2*)(loB + off) = lw;
}
// 2 floats -> packed bf16 hi + lo words
__device__ __forceinline__ void cvt2(float a, float b, uint32_t& hi, uint32_t& lo) {
    __nv_bfloat16 ha = __float2bfloat16(a), hb = __float2bfloat16(b);
    __nv_bfloat16 la = __float2bfloat16(a - __bfloat162float(ha));
    __nv_bfloat16 lb = __float2bfloat16(b - __bfloat162float(hb));
    hi = (uint32_t)__bfloat16_as_ushort(ha) | ((uint32_t)__bfloat16_as_ushort(hb) << 16);
    lo = (uint32_t)__bfloat16_as_ushort(la) | ((uint32_t)__bfloat16_as_ushort(lb) << 16);
}

// ================= fused stage kernel =================
// One block = one (b, h): 64 rows. E -> se (smem) -> K/Q/V (smem) -> scores (mma)
// -> softmax -> w (gmem) -> w@v -> x slice (gmem).
// Full-width bf16 tiles: pitch 272B (17*16 -> conflict-free ldmatrix).
// K-chunk staging tiles: pitch 144B (9*16).
#define FP 272
#define CP 144
// smem offsets (bytes)
#define O_SEH 0
#define O_SEL 17408
#define O_QH  34816
#define O_QL  52224
#define O_KH  69632
#define O_KL  87040
#define O_AH  104448
#define O_AL  113664
#define O_WH  122880
#define O_WL  141312
#define O_VS  159744
#define O_SS  167936
#define STAGE_SMEM (167936 + 64 * 68 * 4)   // 185344

template <int KIN>
__global__ __launch_bounds__(256) void stage_kernel(
    const float* __restrict__ xin,
    const float* __restrict__ Ew, const float* __restrict__ Eb,
    const float* __restrict__ Kw, const float* __restrict__ Kb,
    const float* __restrict__ Qw, const float* __restrict__ Qb,
    const float* __restrict__ Vw, const float* __restrict__ Vb,
    float* __restrict__ wout, float* __restrict__ xout)
{
    extern __shared__ char smc[];
    const uint32_t base = smem_u32(smc);
    char* aHc = smc + O_AH;  char* aLc = smc + O_AL;
    char* wHc = smc + O_WH;  char* wLc = smc + O_WL;
    float* vs = (float*)(smc + O_VS);   // [64][32] fp32
    float* ss = (float*)(smc + O_SS);   // [64][68] fp32

    const int b = blockIdx.x, h = blockIdx.y;
    const int rowBase = b * 64;
    Ew += (long)h * 128 * KIN; Eb += h * 128;
    Kw += (long)h * 128 * 128; Kb += h * 128;
    Qw += (long)h * 128 * 128; Qb += h * 128;
    Vw += (long)h * 32 * 128;  Vb += h * 32;

    const int tid = threadIdx.x;
    const int lane = tid & 31, w = tid >> 5;
    const int wrow = (w >> 1) * 16;          // 4 m-warps
    const int wn   = w & 1;                  // 2 n-warps
    const int wcol  = wn * 64;               // N=128 phases
    const int wcolV = wn * 16;               // N=32 phase
    const int wcolS = wn * 32;               // N=64 phase
    const int aRow  = wrow + (lane & 15);
    const uint32_t aColB = (uint32_t)((lane >> 4) << 4);       // 0/16 B
    const int bN = ((lane >> 4) << 3) + (lane & 7);
    const uint32_t bKB = (uint32_t)(((lane >> 3) & 1) << 4);   // 0/16 B
    const int g = lane >> 2, t = lane & 3;

    // ================== Phase E: se = leaky(x @ Ew^T + Eb) ==================
    {
        float acc[8][4] = {};
        for (int kc = 0; kc < KIN; kc += 64) {
            #pragma unroll
            for (int it = 0; it < 4; it++) {             // A chunk [64 x 64]
                int idx = tid + it * 256;
                int row = idx >> 4, c4 = (idx & 15) << 2;
                float4 v = *(const float4*)&xin[(long)(rowBase + row) * KIN + kc + c4];
                cvt_store(v, aHc, aLc, (uint32_t)(row * CP + c4 * 2));
            }
            #pragma unroll
            for (int it = 0; it < 8; it++) {             // W chunk [128 x 64]
                int idx = tid + it * 256;
                int row = idx >> 4, c4 = (idx & 15) << 2;
                float4 v = *(const float4*)&Ew[(long)row * KIN + kc + c4];
                cvt_store(v, wHc, wLc, (uint32_t)(row * CP + c4 * 2));
            }
            __syncthreads();
            #pragma unroll
            for (int ks = 0; ks < 4; ks++) {
                const uint32_t k0B = (uint32_t)(ks * 32);
                uint32_t ah[4], al[4];
                uint32_t ao = (uint32_t)aRow * CP + k0B + aColB;
                ldsm_x4(ah, base + O_AH + ao);
                ldsm_x4(al, base + O_AL + ao);
                #pragma unroll
                for (int np = 0; np < 4; np++) {
                    uint32_t bo = (uint32_t)((wcol + np * 16 + bN) * CP) + k0B + bKB;
                    uint32_t bh[4], bl[4];
                    ldsm_x4(bh, base + O_WH + bo);
                    ldsm_x4(bl, base + O_WL + bo);
                    #pragma unroll
                    for (int s = 0; s < 2; s++) {
                        mma16816(acc[np * 2 + s], ah, &bh[2 * s]);
                        mma16816(acc[np * 2 + s], ah, &bl[2 * s]);
                        mma16816(acc[np * 2 + s], al, &bh[2 * s]);
                    }
                }
            }
            __syncthreads();
        }
        // epilogue -> se (bf16 hi/lo, pitch FP)
        #pragma unroll
        for (int ni = 0; ni < 8; ni++) {
            int col = wcol + ni * 8 + 2 * t;
            float b0 = Eb[col], b1 = Eb[col + 1];
            int r0 = wrow + g;
            float v0 = LEAKY(acc[ni][0] + b0), v1 = LEAKY(acc[ni][1] + b1);
            float v2 = LEAKY(acc[ni][2] + b0), v3 = LEAKY(acc[ni][3] + b1);
            uint32_t hi, lo;
            cvt2(v0, v1, hi, lo);
            *(uint32_t*)(smc + O_SEH + r0 * FP + col * 2) = hi;
            *(uint32_t*)(smc + O_SEL + r0 * FP + col * 2) = lo;
            cvt2(v2, v3, hi, lo);
            *(uint32_t*)(smc + O_SEH + (r0 + 8) * FP + col * 2) = hi;
            *(uint32_t*)(smc + O_SEL + (r0 + 8) * FP + col * 2) = lo;
        }
        __syncthreads();
    }

    // ================== Phase K / Q: se @ W^T + bias ==================
    #pragma unroll
    for (int tgt = 0; tgt < 2; tgt++) {
        const float* Wp = tgt ? Qw : Kw;
        const float* Bp = tgt ? Qb : Kb;
        const uint32_t OD_H = tgt ? O_QH : O_KH;
        const uint32_t OD_L = tgt ? O_QL : O_KL;
        float acc[8][4] = {};
        for (int kc = 0; kc < 128; kc += 64) {
            #pragma unroll
            for (int it = 0; it < 8; it++) {
                int idx = tid + it * 256;
                int row = idx >> 4, c4 = (idx & 15) << 2;
                float4 v = *(const float4*)&Wp[(long)row * 128 + kc + c4];
                cvt_store(v, wHc, wLc, (uint32_t)(row * CP + c4 * 2));
            }
            __syncthreads();
            #pragma unroll
            for (int ks = 0; ks < 4; ks++) {
                const uint32_t kse = (uint32_t)(kc * 2 + ks * 32);
                const uint32_t k0B = (uint32_t)(ks * 32);
                uint32_t ah[4], al[4];
                uint32_t ao = (uint32_t)aRow * FP + kse + aColB;
                ldsm_x4(ah, base + O_SEH + ao);
                ldsm_x4(al, base + O_SEL + ao);
                #pragma unroll
                for (int np = 0; np < 4; np++) {
                    uint32_t bo = (uint32_t)((wcol + np * 16 + bN) * CP) + k0B + bKB;
                    uint32_t bh[4], bl[4];
                    ldsm_x4(bh, base + O_WH + bo);
                    ldsm_x4(bl, base + O_WL + bo);
                    #pragma unroll
                    for (int s = 0; s < 2; s++) {
                        mma16816(acc[np * 2 + s], ah, &bh[2 * s]);
                        mma16816(acc[np * 2 + s], ah, &bl[2 * s]);
                        mma16816(acc[np * 2 + s], al, &bh[2 * s]);
                    }
                }
            }
            __syncthreads();
        }
        #pragma unroll
        for (int ni = 0; ni < 8; ni++) {
            int col = wcol + ni * 8 + 2 * t;
            float b0 = Bp[col], b1 = Bp[col + 1];
            int r0 = wrow + g;
            uint32_t hi, lo;
            cvt2(acc[ni][0] + b0, acc[ni][1] + b1, hi, lo);
            *(uint32_t*)(smc + OD_H + r0 * FP + col * 2) = hi;
            *(uint32_t*)(smc + OD_L + r0 * FP + col * 2) = lo;
            cvt2(acc[ni][2] + b0, acc[ni][3] + b1, hi, lo);
            *(uint32_t*)(smc + OD_H + (r0 + 8) * FP + col * 2) = hi;
            *(uint32_t*)(smc + OD_L + (r0 + 8) * FP + col * 2) = lo;
        }
        __syncthreads();
    }

    // ================== Phase V: v = leaky(se @ Vw^T + Vb)  (N=32, fp32 out) ==================
    {
        float acc[2][4] = {};
        for (int kc = 0; kc < 128; kc += 64) {
            #pragma unroll
            for (int it = 0; it < 2; it++) {
                int idx = tid + it * 256;
                int row = idx >> 4, c4 = (idx & 15) << 2;
                float4 v = *(const float4*)&Vw[(long)row * 128 + kc + c4];
                cvt_store(v, wHc, wLc, (uint32_t)(row * CP + c4 * 2));
            }
            __syncthreads();
            #pragma unroll
            for (int ks = 0; ks < 4; ks++) {
                const uint32_t kse = (uint32_t)(kc * 2 + ks * 32);
                const uint32_t k0B = (uint32_t)(ks * 32);
                uint32_t ah[4], al[4];
                uint32_t ao = (uint32_t)aRow * FP + kse + aColB;
                ldsm_x4(ah, base + O_SEH + ao);
                ldsm_x4(al, base + O_SEL + ao);
                uint32_t bo = (uint32_t)((wcolV + bN) * CP) + k0B + bKB;
                uint32_t bh[4], bl[4];
                ldsm_x4(bh, base + O_WH + bo);
                ldsm_x4(bl, base + O_WL + bo);
                #pragma unroll
                for (int s = 0; s < 2; s++) {
                    mma16816(acc[s], ah, &bh[2 * s]);
                    mma16816(acc[s], ah, &bl[2 * s]);
                    mma16816(acc[s], al, &bh[2 * s]);
                }
            }
            __syncthreads();
        }
        #pragma unroll
        for (int ni = 0; ni < 2; ni++) {
            int col = wcolV + ni * 8 + 2 * t;
            float b0 = Vb[col], b1 = Vb[col + 1];
            int r0 = wrow + g;
            vs[r0 * 32 + col]           = LEAKY(acc[ni][0] + b0);
            vs[r0 * 32 + col + 1]       = LEAKY(acc[ni][1] + b1);
            vs[(r0 + 8) * 32 + col]     = LEAKY(acc[ni][2] + b0);
            vs[(r0 + 8) * 32 + col + 1] = LEAKY(acc[ni][3] + b1);
        }
        __syncthreads();
    }

    // ================== Phase scores: q @ k^T (N=64), scale ==================
    {
        float acc[4][4] = {};
        #pragma unroll
        for (int ks = 0; ks < 8; ks++) {
            const uint32_t k0B = (uint32_t)(ks * 32);
            uint32_t ah[4], al[4];
            uint32_t ao = (uint32_t)aRow * FP + k0B + aColB;
            ldsm_x4(ah, base + O_QH + ao);
            ldsm_x4(al, base + O_QL + ao);
            #pragma unroll
            for (int np = 0; np < 2; np++) {
                uint32_t bo = (uint32_t)((wcolS + np * 16 + bN) * FP) + k0B + bKB;
                uint32_t bh[4], bl[4];
                ldsm_x4(bh, base + O_KH + bo);
                ldsm_x4(bl, base + O_KL + bo);
                #pragma unroll
                for (int s = 0; s < 2; s++) {
                    mma16816(acc[np * 2 + s], ah, &bh[2 * s]);
                    mma16816(acc[np * 2 + s], ah, &bl[2 * s]);
                    mma16816(acc[np * 2 + s], al, &bh[2 * s]);
                }
            }
        }
        const float scale = 0.088388347648318447f;   // 1/sqrt(128)
        #pragma unroll
        for (int ni = 0; ni < 4; ni++) {
            int col = wcolS + ni * 8 + 2 * t;
            int r0 = wrow + g;
            ss[r0 * 68 + col]           = acc[ni][0] * scale;
            ss[r0 * 68 + col + 1]       = acc[ni][1] * scale;
            ss[(r0 + 8) * 68 + col]     = acc[ni][2] * scale;
            ss[(r0 + 8) * 68 + col + 1] = acc[ni][3] * scale;
        }
        __syncthreads();
    }

    // ================== softmax rows ==================
    if (tid < 64) {
        float mx = -1e30f;
        for (int m = 0; m < 64; m++) mx = fmaxf(mx, ss[tid * 68 + m]);
        float s = 0.f;
        for (int m = 0; m < 64; m++) {
            float e = __expf(ss[tid * 68 + m] - mx);
            ss[tid * 68 + m] = e; s += e;
        }
        float inv = 1.f / s;
        for (int m = 0; m < 64; m++) ss[tid * 68 + m] *= inv;
    }
    __syncthreads();

    // ---- write w ----
    float* wp = wout + ((long)h * 512 + b) * 4096;
    for (int i = tid; i < 4096; i += 256)
        wp[i] = ss[(i >> 6) * 68 + (i & 63)];

    // ---- att = w @ v (fp32), write x slice ----
    {
        const int o4 = tid & 7;
        const int n0 = tid >> 3;
        float r0[4] = {}, r1[4] = {};
        #pragma unroll 4
        for (int m4 = 0; m4 < 16; m4++) {
            float4 aA = *(const float4*)&ss[n0 * 68 + m4 * 4];
            float4 aB = *(const float4*)&ss[(n0 + 32) * 68 + m4 * 4];
            #pragma unroll
            for (int s = 0; s < 4; s++) {
                float4 bb = *(const float4*)&vs[(m4 * 4 + s) * 32 + o4 * 4];
                float am = (&aA.x)[s], bm = (&aB.x)[s];
                #pragma unroll
                for (int j = 0; j < 4; j++) {
                    r0[j] = fmaf(am, (&bb.x)[j], r0[j]);
                    r1[j] = fmaf(bm, (&bb.x)[j], r1[j]);
                }
            }
        }
        *(float4*)&xout[((long)rowBase + n0)      * 128 + h * 32 + o4 * 4] = *(float4*)&r0[0];
        *(float4*)&xout[((long)rowBase + n0 + 32) * 128 + h * 32 + o4 * 4] = *(float4*)&r1[0];
    }
}

// ================= final MLP + softmax =================
#define HEAD_SMEM ((64 * 128 + 128 * 68 + 64 * 68 + 64 * 20 + 64 * 16) * 4)

__global__ __launch_bounds__(256) void head_kernel(
    const float* __restrict__ x,
    const float* __restrict__ F1w, const float* __restrict__ F1b,
    const float* __restrict__ F2w, const float* __restrict__ F2b,
    float* __restrict__ pol)
{
    extern __shared__ float sm[];
    float* xs  = sm;
    float* f1t = xs + 64 * 128;
    float* hs  = f1t + 128 * 68;
    float* f2t = hs + 64 * 68;
    float* ls  = f2t + 64 * 20;

    const int b = blockIdx.x, tid = threadIdx.x;
    const float* xp = x + (long)b * 64 * 128;

    for (int i = tid; i < 2048; i += 256) ((float4*)xs)[i] = ((const float4*)xp)[i];
    for (int i = tid; i < 8192; i += 256) {
        int c = i >> 7, d = i & 127;
        f1t[d * 68 + c] = F1w[i];
    }
    for (int i = tid; i < 1024; i += 256) {
        int p = i >> 6, c = i & 63;
        f2t[c * 20 + p] = F2w[i];
    }
    __syncthreads();

    const int tx = tid & 15, ty = tid >> 4;
    float acc[4][4] = {};
    #pragma unroll 4
    for (int d4 = 0; d4 < 32; d4++) {
        float4 a0 = *(const float4*)&xs[(ty * 4 + 0) * 128 + d4 * 4];
        float4 a1 = *(const float4*)&xs[(ty * 4 + 1) * 128 + d4 * 4];
        float4 a2 = *(const float4*)&xs[(ty * 4 + 2) * 128 + d4 * 4];
        float4 a3 = *(const float4*)&xs[(ty * 4 + 3) * 128 + d4 * 4];
        float4 b0 = *(const float4*)&f1t[(d4 * 4 + 0) * 68 + tx * 4];
        float4 b1 = *(const float4*)&f1t[(d4 * 4 + 1) * 68 + tx * 4];
        float4 b2 = *(const float4*)&f1t[(d4 * 4 + 2) * 68 + tx * 4];
        float4 b3 = *(const float4*)&f1t[(d4 * 4 + 3) * 68 + tx * 4];
        const float4 aa[4] = {a0, a1, a2, a3};
        #pragma unroll
        for (int i = 0; i < 4; i++)
            #pragma unroll
            for (int j = 0; j < 4; j++) {
                float s = acc[i][j];
                s = fmaf(aa[i].x, (&b0.x)[j], s);
                s = fmaf(aa[i].y, (&b1.x)[j], s);
                s = fmaf(aa[i].z, (&b2.x)[j], s);
                s = fmaf(aa[i].w, (&b3.x)[j], s);
                acc[i][j] = s;
            }
    }
    #pragma unroll
    for (int i = 0; i < 4; i++) {
        float r[4];
        #pragma unroll
        for (int j = 0; j < 4; j++) {
            float v = acc[i][j] + F1b[tx * 4 + j];
            r[j] = LEAKY(v);
        }
        *(float4*)&hs[(ty * 4 + i) * 68 + tx * 4] = *(float4*)&r[0];
    }
    __syncthreads();

    {
        const int p4 = tid & 3;
        const int n  = tid >> 2;
        float acc2[4];
        #pragma unroll
        for (int j = 0; j < 4; j++) acc2[j] = F2b[p4 * 4 + j];
        #pragma unroll 4
        for (int c4 = 0; c4 < 16; c4++) {
            float4 a = *(const float4*)&hs[n * 68 + c4 * 4];
            #pragma unroll
            for (int s = 0; s < 4; s++) {
                float4 bb = *(const float4*)&f2t[(c4 * 4 + s) * 20 + p4 * 4];
                float am = (&a.x)[s];
                #pragma unroll
                for (int j = 0; j < 4; j++)
                    acc2[j] = fmaf(am, (&bb.x)[j], acc2[j]);
            }
        }
        *(float4*)&ls[n * 16 + p4 * 4] = *(float4*)&acc2[0];
    }
    __syncthreads();

    if (tid < 64) {
        float mx = -1e30f;
        for (int p = 0; p < 16; p++) mx = fmaxf(mx, ls[tid * 16 + p]);
        float s = 0.f;
        for (int p = 0; p < 16; p++) {
            float e = __expf(ls[tid * 16 + p] - mx);
            ls[tid * 16 + p] = e; s += e;
        }
        float inv = 1.f / s;
        for (int p = 0; p < 16; p++) ls[tid * 16 + p] *= inv;
    }
    __syncthreads();

    float* pp = pol + (long)b * 1024;
    #pragma unroll
    for (int e = 0; e < 4; e++) { int idx = tid + e * 256; pp[idx] = ls[idx]; }
}

// ---------------- launch ----------------
extern "C" void kernel_launch(void* const* d_in, const int* in_sizes, int n_in,
                              void* d_out, int out_size)
{
    const float* states = (const float*)d_in[0];
    const float* E1w = (const float*)d_in[1];  const float* E1b = (const float*)d_in[2];
    const float* K1w = (const float*)d_in[3];  const float* K1b = (const float*)d_in[4];
    const float* Q1w = (const float*)d_in[5];  const float* Q1b = (const float*)d_in[6];
    const float* V1w = (const float*)d_in[7];  const float* V1b = (const float*)d_in[8];
    const float* E2w = (const float*)d_in[9];  const float* E2b = (const float*)d_in[10];
    const float* K2w = (const float*)d_in[11]; const float* K2b = (const float*)d_in[12];
    const float* Q2w = (const float*)d_in[13]; const float* Q2b = (const float*)d_in[14];
    const float* V2w = (const float*)d_in[15]; const float* V2b = (const float*)d_in[16];
    const float* F1w = (const float*)d_in[17]; const float* F1b = (const float*)d_in[18];
    const float* F2w = (const float*)d_in[19]; const float* F2b = (const float*)d_in[20];
    float* out = (float*)d_out;

    float *xx, *xx2;
    cudaGetSymbolAddress((void**)&xx,  g_x);
    cudaGetSymbolAddress((void**)&xx2, g_x2);

    cudaFuncSetAttribute(stage_kernel<256>, cudaFuncAttributeMaxDynamicSharedMemorySize, STAGE_SMEM);
    cudaFuncSetAttribute(stage_kernel<128>, cudaFuncAttributeMaxDynamicSharedMemorySize, STAGE_SMEM);
    cudaFuncSetAttribute(head_kernel, cudaFuncAttributeMaxDynamicSharedMemorySize, HEAD_SMEM);

    float* w1out = out + 512L * 64 * 16;
    float* w2out = w1out + 4L * 512 * 64 * 64;
    dim3 blk(256), grd(512, 4);

    stage_kernel<256><<<grd, blk, STAGE_SMEM>>>(states, E1w, E1b, K1w, K1b, Q1w, Q1b, V1w, V1b, w1out, xx);
    stage_kernel<128><<<grd, blk, STAGE_SMEM>>>(xx,     E2w, E2b, K2w, K2b, Q2w, Q2b, V2w, V2b, w2out, xx2);
    head_kernel<<<512, blk, HEAD_SMEM>>>(xx2, F1w, F1b, F2w, F2b, out);
}